// round 1
// baseline (speedup 1.0000x reference)
#include <cuda_runtime.h>

#define NB 64
#define T_DEC 2048
#define T_ENC 512
#define G_STEPS 20000
// ln(0.99995), high precision
#define LN_GAMMA (-5.0001250041667e-05)

__device__ double g_scratch;

__global__ void gal_init_kernel() {
    g_scratch = 0.0;
}

__global__ __launch_bounds__(256) void gal_main_kernel(
    const float* __restrict__ A,      // [NB, T_DEC, T_ENC]
    const int*   __restrict__ inL,    // [NB]
    const int*   __restrict__ tgtL,   // [NB]
    const int*   __restrict__ gstep)  // [1]
{
    const int step = *gstep;
    if (step > G_STEPS) return;   // finalize writes 0 in that case

    // inv_denom = 1/(2 g^2), g = gamma^step. Compute once in double per thread (cheap, uniform).
    const double gd = exp((double)step * LN_GAMMA);
    const float inv_denom = (float)(0.5 / (gd * gd));

    __shared__ float s_invL[NB], s_invF[NB], s_scale[NB];
    __shared__ int   s_L[NB], s_F[NB];

    const int tid = threadIdx.x;
    if (tid < NB) {
        const int L = inL[tid];
        const int F = tgtL[tid];
        s_L[tid] = L;
        s_F[tid] = F;
        s_invL[tid]  = 1.0f / (float)L;
        s_invF[tid]  = 1.0f / (float)F;
        s_scale[tid] = 1.0f / ((float)F * (float)NB);
    }
    __syncthreads();

    float acc = 0.0f;
    const int c0 = tid * 2;           // each thread owns 2 contiguous columns via float2
    const float lc0 = (float)c0;
    const float lc1 = (float)(c0 + 1);

    const int total_rows = NB * T_DEC;
    for (int row = blockIdx.x; row < total_rows; row += gridDim.x) {
        const int b = row >> 11;              // row / T_DEC
        const int f = row & (T_DEC - 1);      // row % T_DEC
        if (f >= s_F[b]) continue;            // masked rows: skip (no DRAM read)
        const int L = s_L[b];
        if (c0 >= L) continue;                // masked columns: skip

        const float2 a = *((const float2*)(A + ((size_t)row << 9)) + tid);

        const float invL = s_invL[b];
        const float fF   = (float)f * s_invF[b];
        const float d0 = fmaf(lc0, invL, -fF);
        const float d1 = fmaf(lc1, invL, -fF);
        const float w0 = 1.0f - __expf(-d0 * d0 * inv_denom);
        const float w1 = 1.0f - __expf(-d1 * d1 * inv_denom);

        float v = w0 * a.x;
        if (c0 + 1 < L) v = fmaf(w1, a.y, v);
        acc = fmaf(v, s_scale[b], acc);
    }

    // block reduction: warp shuffle -> shared -> warp 0 -> one double atomic
    #pragma unroll
    for (int o = 16; o > 0; o >>= 1)
        acc += __shfl_down_sync(0xffffffffu, acc, o);

    __shared__ float warpsum[8];
    const int wid = tid >> 5, lid = tid & 31;
    if (lid == 0) warpsum[wid] = acc;
    __syncthreads();
    if (wid == 0) {
        float v = (lid < 8) ? warpsum[lid] : 0.0f;
        #pragma unroll
        for (int o = 4; o > 0; o >>= 1)
            v += __shfl_down_sync(0xffu, v, o);
        if (lid == 0) atomicAdd(&g_scratch, (double)v);
    }
}

__global__ void gal_finalize_kernel(const int* __restrict__ gstep, float* __restrict__ out) {
    out[0] = (*gstep > G_STEPS) ? 0.0f : (float)g_scratch;
}

extern "C" void kernel_launch(void* const* d_in, const int* in_sizes, int n_in,
                              void* d_out, int out_size) {
    const float* A    = (const float*)d_in[0];
    const int* inL    = (const int*)d_in[1];
    const int* tgtL   = (const int*)d_in[2];
    const int* gstep  = (const int*)d_in[3];
    float* out        = (float*)d_out;

    gal_init_kernel<<<1, 1>>>();
    // 8 blocks of 256 threads per SM (2048 thr/SM) x 148 SMs
    gal_main_kernel<<<1184, 256>>>(A, inL, tgtL, gstep);
    gal_finalize_kernel<<<1, 1>>>(gstep, out);
}

// round 3
// speedup vs baseline: 1.5880x; 1.5880x over previous
#include <cuda_runtime.h>

#define NB 64
#define TD 2048
#define TE 512
#define G_STEPS 20000
// ln(0.99995), high precision
#define LN_GAMMA (-5.0001250041667e-05)
#define LOG2E 1.4426950408889634
#define GRID 1184
#define CHUNK_SHIFT 5               // 32 rows per chunk
#define CHUNKS_PER_B (TD >> CHUNK_SHIFT)   // 64
#define NCHUNK (NB * CHUNKS_PER_B)         // 4096

__device__ float g_partial[GRID];

// MUFU ex2 regardless of fast-math flags
__device__ __forceinline__ float ex2_approx(float x) {
    float r;
    asm("ex2.approx.f32 %0, %1;" : "=f"(r) : "f"(x));
    return r;
}

// per-4-element contribution: facc += sum_j w_j * v_j (mask applied to v)
__device__ __forceinline__ void gal_acc(float& facc, float4 v, float y,
                                        float a0, float a1, float a2, float a3,
                                        float m1, float m2, float m3, float kneg)
{
    const float d0 = a0 - y, d1 = a1 - y, d2 = a2 - y, d3 = a3 - y;
    const float w0 = 1.0f - ex2_approx(d0 * d0 * kneg);
    const float w1 = 1.0f - ex2_approx(d1 * d1 * kneg);
    const float w2 = 1.0f - ex2_approx(d2 * d2 * kneg);
    const float w3 = 1.0f - ex2_approx(d3 * d3 * kneg);
    facc = fmaf(w0, v.x, facc);
    facc = fmaf(w1, v.y * m1, facc);
    facc = fmaf(w2, v.z * m2, facc);
    facc = fmaf(w3, v.w * m3, facc);
}

__global__ __launch_bounds__(256) void gal_main_kernel(
    const float* __restrict__ A,      // [NB, TD, TE]
    const int*   __restrict__ inL,    // [NB]
    const int*   __restrict__ tgtL,   // [NB]
    const int*   __restrict__ gstep)  // [1]
{
    const int tid = threadIdx.x;
    float partial = 0.0f;
    const int step = *gstep;

    if (step <= G_STEPS) {
        const double gd = exp((double)step * LN_GAMMA);
        const float kneg = (float)(-(0.5 / (gd * gd)) * LOG2E); // w=1-exp2(d^2*kneg)

        const int half = tid >> 7;            // 0/1 : which row of the pair
        const int cidx = (tid & 127) << 2;    // float4 column start (covers 512 cols)
        const float fc0 = (float)cidx;

        for (int ch = blockIdx.x; ch < NCHUNK; ch += GRID) {
            const int b  = ch >> 6;                       // chunk -> batch
            const int r0 = (ch & (CHUNKS_PER_B - 1)) << CHUNK_SHIFT;
            const int F = tgtL[b];
            if (r0 >= F) continue;                        // fully masked chunk
            const int L = inL[b];
            if (cidx >= L) continue;                      // fully masked columns

            const float invL = 1.0f / (float)L;
            const float invF = 1.0f / (float)F;
            const float scale = 1.0f / ((float)F * (float)NB);
            const float a0 = fc0 * invL;
            const float a1 = (fc0 + 1.0f) * invL;
            const float a2 = (fc0 + 2.0f) * invL;
            const float a3 = (fc0 + 3.0f) * invL;
            const float m1 = (cidx + 1 < L) ? 1.0f : 0.0f;
            const float m2 = (cidx + 2 < L) ? 1.0f : 0.0f;
            const float m3 = (cidx + 3 < L) ? 1.0f : 0.0f;

            const int rows = min(32, F - r0);             // valid rows in chunk
            const float* p = A + ((size_t)b << 20) + ((size_t)(r0 + half) << 9) + cidx;
            const float ybase = (float)(r0 + half) * invF;
            const float ystep2 = 2.0f * invF;             // per pass (2 rows)

            float facc = 0.0f;
            int r = half;                                 // row offset within chunk
            float y = ybase;
            const int nfull = rows >> 3;                  // full 8-row iterations

            for (int it = 0; it < nfull; ++it) {
                // 4 independent loads, front-batched -> MLP 4
                const float4 v0 = __ldg((const float4*)(p));
                const float4 v1 = __ldg((const float4*)(p + 1024));
                const float4 v2 = __ldg((const float4*)(p + 2048));
                const float4 v3 = __ldg((const float4*)(p + 3072));
                p += 4096;
                gal_acc(facc, v0, y,               a0, a1, a2, a3, m1, m2, m3, kneg);
                gal_acc(facc, v1, y + ystep2,      a0, a1, a2, a3, m1, m2, m3, kneg);
                gal_acc(facc, v2, y + 2.f*ystep2,  a0, a1, a2, a3, m1, m2, m3, kneg);
                gal_acc(facc, v3, y + 3.f*ystep2,  a0, a1, a2, a3, m1, m2, m3, kneg);
                y += 4.0f * ystep2;
                r += 8;
            }
            // tail (up to 7 remaining rows; this thread's rows are r, r+2, r+4, r+6)
            #pragma unroll
            for (int q = 0; q < 4; ++q) {
                if (r + 2 * q < rows) {
                    const float4 v = __ldg((const float4*)(p + q * 1024));
                    gal_acc(facc, v, y + (float)q * ystep2,
                            a0, a1, a2, a3, m1, m2, m3, kneg);
                }
            }
            partial = fmaf(facc, scale, partial);
        }
    }

    // block reduction -> one partial per block (no atomics, no init kernel)
    #pragma unroll
    for (int o = 16; o > 0; o >>= 1)
        partial += __shfl_down_sync(0xffffffffu, partial, o);

    __shared__ float warpsum[8];
    const int wid = tid >> 5, lid = tid & 31;
    if (lid == 0) warpsum[wid] = partial;
    __syncthreads();
    if (wid == 0) {
        float v = (lid < 8) ? warpsum[lid] : 0.0f;
        #pragma unroll
        for (int o = 4; o > 0; o >>= 1)
            v += __shfl_down_sync(0xffu, v, o);
        if (lid == 0) g_partial[blockIdx.x] = v;
    }
}

__global__ __launch_bounds__(1024) void gal_finalize_kernel(
    const int* __restrict__ gstep, float* __restrict__ out)
{
    const int t = threadIdx.x;
    float s = 0.0f;
    if (*gstep <= G_STEPS) {
        for (int i = t; i < GRID; i += 1024) s += g_partial[i];
    }
    #pragma unroll
    for (int o = 16; o > 0; o >>= 1)
        s += __shfl_down_sync(0xffffffffu, s, o);

    __shared__ float sm[32];
    if ((t & 31) == 0) sm[t >> 5] = s;
    __syncthreads();
    if (t < 32) {
        float v = sm[t];
        #pragma unroll
        for (int o = 16; o > 0; o >>= 1)
            v += __shfl_down_sync(0xffffffffu, v, o);
        if (t == 0) out[0] = v;
    }
}

extern "C" void kernel_launch(void* const* d_in, const int* in_sizes, int n_in,
                              void* d_out, int out_size) {
    const float* A   = (const float*)d_in[0];
    const int* inL   = (const int*)d_in[1];
    const int* tgtL  = (const int*)d_in[2];
    const int* gstep = (const int*)d_in[3];
    float* out       = (float*)d_out;

    gal_main_kernel<<<GRID, 256>>>(A, inL, tgtL, gstep);
    gal_finalize_kernel<<<1, 1024>>>(gstep, out);
}

// round 4
// speedup vs baseline: 1.8110x; 1.1404x over previous
#include <cuda_runtime.h>

#define NB 64
#define TD 2048
#define TE 512
#define G_STEPS 20000
#define LN_GAMMA (-5.0001250041667e-05)   // ln(0.99995)
#define LOG2E 1.4426950408889634
#define GRID 888                          // 148 SMs x 6 blocks
#define CHUNK_SHIFT 3                     // 8 rows per unit
#define CHUNKS_PER_B (TD >> CHUNK_SHIFT)  // 256
#define NCHUNK (NB * CHUNKS_PER_B)        // 16384

__device__ float g_partial[GRID];
__device__ unsigned int g_ticket = 0;     // self-resetting, graph-replay safe

__device__ __forceinline__ float ex2_approx(float x) {
    float r;
    asm("ex2.approx.f32 %0, %1;" : "=f"(r) : "f"(x));
    return r;
}

__device__ __forceinline__ void gal_acc(float& facc, float4 v, float y,
                                        float a0, float a1, float a2, float a3,
                                        float m1, float m2, float m3, float kneg)
{
    const float d0 = a0 - y, d1 = a1 - y, d2 = a2 - y, d3 = a3 - y;
    const float w0 = 1.0f - ex2_approx(d0 * d0 * kneg);
    const float w1 = 1.0f - ex2_approx(d1 * d1 * kneg);
    const float w2 = 1.0f - ex2_approx(d2 * d2 * kneg);
    const float w3 = 1.0f - ex2_approx(d3 * d3 * kneg);
    facc = fmaf(w0, v.x, facc);
    facc = fmaf(w1, v.y * m1, facc);
    facc = fmaf(w2, v.z * m2, facc);
    facc = fmaf(w3, v.w * m3, facc);
}

__global__ void __launch_bounds__(256, 6) gal_main_kernel(
    const float* __restrict__ A,      // [NB, TD, TE]
    const int*   __restrict__ inL,    // [NB]
    const int*   __restrict__ tgtL,   // [NB]
    const int*   __restrict__ gstep,  // [1]
    float*       __restrict__ out)    // [1]
{
    __shared__ float s_invL[NB], s_invF[NB], s_scale[NB];
    __shared__ int   s_L[NB], s_F[NB];
    __shared__ float warpsum[8];
    __shared__ int   s_last;

    const int tid = threadIdx.x;
    if (tid < NB) {
        const int L = inL[tid];
        const int F = tgtL[tid];
        s_L[tid] = L;
        s_F[tid] = F;
        s_invL[tid]  = 1.0f / (float)L;
        s_invF[tid]  = 1.0f / (float)F;
        s_scale[tid] = 1.0f / ((float)F * (float)NB);
    }
    __syncthreads();

    float partial = 0.0f;
    const int step = *gstep;

    if (step <= G_STEPS) {
        const double gd = exp((double)step * LN_GAMMA);
        const float kneg = (float)(-(0.5 / (gd * gd)) * LOG2E);

        const int half = tid >> 7;            // 0/1: row parity within the unit
        const int cidx = (tid & 127) << 2;    // float4 column start
        const float fc0 = (float)cidx;

        for (int ch = blockIdx.x; ch < NCHUNK; ch += GRID) {
            const int b  = ch >> 8;                              // unit -> batch
            const int r0 = (ch & (CHUNKS_PER_B - 1)) << CHUNK_SHIFT;
            const int F = s_F[b];
            if (r0 >= F) continue;
            const int L = s_L[b];
            if (cidx >= L) continue;

            const float invL = s_invL[b];
            const float invF = s_invF[b];
            const float a0 = fc0 * invL;
            const float a1 = (fc0 + 1.0f) * invL;
            const float a2 = (fc0 + 2.0f) * invL;
            const float a3 = (fc0 + 3.0f) * invL;
            const float m1 = (cidx + 1 < L) ? 1.0f : 0.0f;
            const float m2 = (cidx + 2 < L) ? 1.0f : 0.0f;
            const float m3 = (cidx + 3 < L) ? 1.0f : 0.0f;

            const int rows = min(8, F - r0);
            const float* p = A + ((size_t)b << 20) + ((size_t)(r0 + half) << 9) + cidx;
            const float y0 = (float)(r0 + half) * invF;
            const float ys = 2.0f * invF;

            float facc = 0.0f;
            if (rows == 8) {
                // fast path: 4 independent float4 loads front-batched (MLP 4)
                const float4 v0 = __ldg((const float4*)(p));
                const float4 v1 = __ldg((const float4*)(p + 1024));
                const float4 v2 = __ldg((const float4*)(p + 2048));
                const float4 v3 = __ldg((const float4*)(p + 3072));
                gal_acc(facc, v0, y0,            a0, a1, a2, a3, m1, m2, m3, kneg);
                gal_acc(facc, v1, y0 + ys,       a0, a1, a2, a3, m1, m2, m3, kneg);
                gal_acc(facc, v2, y0 + 2.f*ys,   a0, a1, a2, a3, m1, m2, m3, kneg);
                gal_acc(facc, v3, y0 + 3.f*ys,   a0, a1, a2, a3, m1, m2, m3, kneg);
            } else {
                #pragma unroll
                for (int q = 0; q < 4; ++q) {
                    if (half + 2 * q < rows) {
                        const float4 v = __ldg((const float4*)(p + q * 1024));
                        gal_acc(facc, v, y0 + (float)q * ys,
                                a0, a1, a2, a3, m1, m2, m3, kneg);
                    }
                }
            }
            partial = fmaf(facc, s_scale[b], partial);
        }
    }

    // block reduction
    #pragma unroll
    for (int o = 16; o > 0; o >>= 1)
        partial += __shfl_down_sync(0xffffffffu, partial, o);
    const int wid = tid >> 5, lid = tid & 31;
    if (lid == 0) warpsum[wid] = partial;
    __syncthreads();
    if (tid == 0) {
        float v = 0.0f;
        #pragma unroll
        for (int w = 0; w < 8; ++w) v += warpsum[w];
        g_partial[blockIdx.x] = v;
        __threadfence();
        const unsigned int t = atomicAdd(&g_ticket, 1u);
        s_last = (t == GRID - 1) ? 1 : 0;
    }
    __syncthreads();

    // last finishing block: fused finalize (saves a kernel launch)
    if (s_last) {
        float s = 0.0f;
        for (int i = tid; i < GRID; i += 256)
            s += __ldcg(&g_partial[i]);
        #pragma unroll
        for (int o = 16; o > 0; o >>= 1)
            s += __shfl_down_sync(0xffffffffu, s, o);
        if (lid == 0) warpsum[wid] = s;
        __syncthreads();
        if (tid == 0) {
            float v = 0.0f;
            #pragma unroll
            for (int w = 0; w < 8; ++w) v += warpsum[w];
            out[0] = v;
            g_ticket = 0;          // reset for next graph replay
            __threadfence();
        }
    }
}

extern "C" void kernel_launch(void* const* d_in, const int* in_sizes, int n_in,
                              void* d_out, int out_size) {
    const float* A   = (const float*)d_in[0];
    const int* inL   = (const int*)d_in[1];
    const int* tgtL  = (const int*)d_in[2];
    const int* gstep = (const int*)d_in[3];
    float* out       = (float*)d_out;

    gal_main_kernel<<<GRID, 256>>>(A, inL, tgtL, gstep, out);
}